// round 10
// baseline (speedup 1.0000x reference)
#include <cuda_runtime.h>

// HakesPQ forward: out[n, m*16:(m+1)*16] = codebooks[m, k*, :]
// k* = argmin_k fl( fl(v2 - fl(2*<v,c_k>)) + |c_k|^2 ), exact fp32 emulation of
// the reference (jax/XLA-CPU): all reductions are sequential fmaf chains over
// d ascending; ties -> lowest k. Arithmetic order is FROZEN (rel_err==0.0).
// N=32768, D=768, M=48, KSUB=16, DSUB=16.
//
// R9: L1-throughput round. R=2 rows/thread (halves codebook LDS), c2 as
// LDS.128, winners stored straight to gmem (no output staging), m-pair
// codebook padding (272) for conflict-free broadcast. 2 CTAs/SM.

#define N_VECS   32768
#define D_DIM    768
#define M_SUB    48
#define KSUB     16
#define DSUB     16

#define MHALF    24                   // m per CTA (blockIdx.y selects half)
#define CHALF    (MHALF * DSUB)       // 384 v-columns per CTA
#define NROWS    32                   // rows per CTA
#define NTHREADS 384                  // 12 warps; warp = adjacent m-pair x 16 row-groups
#define ROW_PAD  388                  // 4*rg mod 32 bank spread, float4 aligned
#define M_PAD    272                  // 256+16: m-pair 16 banks apart on broadcast loads

#define SV_FLOATS   (NROWS * ROW_PAD)          // 12416
#define SCB_FLOATS  (MHALF * M_PAD)            // 6528
#define SC2_FLOATS  (MHALF * KSUB)             // 384
#define SMEM_BYTES  ((SV_FLOATS + SCB_FLOATS + SC2_FLOATS) * 4)   // ~75.8 KB

__global__ void __launch_bounds__(NTHREADS, 2)
pq_kernel(const float* __restrict__ vecs,
          const float* __restrict__ cb,
          float* __restrict__ out)
{
    extern __shared__ float smem[];
    float* sv  = smem;                 // [NROWS][ROW_PAD] v tile
    float* scb = smem + SV_FLOATS;     // [MHALF][M_PAD] codebook half (16..271 used? 0..255 used)
    float* sc2 = scb + SCB_FLOATS;     // [MHALF][KSUB]

    const int tid = threadIdx.x;
    const int mh  = blockIdx.y;
    const float* cb_half = cb + mh * (MHALF * KSUB * DSUB);

    // ---- codebook half into shared with per-m padding (coalesced float4) ----
    {
        const float4* src = (const float4*)cb_half;
        #pragma unroll
        for (int t = 0; t < 4; t++) {                 // 1536 float4 / 384 threads
            int i = tid + t * NTHREADS;
            int m = i >> 6;                           // 64 float4 per m
            int r = i & 63;
            *((float4*)(scb + m * M_PAD) + r) = src[i];
        }
    }
    // ---- |c|^2: one (m,k) per thread, frozen sequential fma chain ----
    {
        const float* c = cb_half + tid * DSUB;        // tid < 384 = MHALF*KSUB
        float s = 0.0f;
        #pragma unroll
        for (int d = 0; d < DSUB; d++) s = fmaf(c[d], c[d], s);
        sc2[tid] = s;
    }

    // ---- stage this CTA's 32x384 v sub-tile (coalesced float4) ----
    const long long row0 = (long long)blockIdx.x * NROWS;
    {
        const float4* vin = (const float4*)(vecs + row0 * D_DIM) + mh * (CHALF / 4);
        const int c4    = tid % (CHALF / 4);          // 0..95
        const int rbase = tid / (CHALF / 4);          // 0..3
        #pragma unroll
        for (int t = 0; t < 8; t++) {
            int r = rbase + t * 4;
            *(float4*)(sv + r * ROW_PAD + c4 * 4) =
                vin[(long long)r * (D_DIM / 4) + c4];
        }
    }
    __syncthreads();

    // ---- two (row, m) tasks per thread: rows rg and rg+16, same m ----
    const int warp = tid >> 5;
    const int lane = tid & 31;
    const int ml   = 2 * warp + (lane >> 4);          // local m, warp = adjacent pair
    const int rg   = lane & 15;

    float* myv0 = sv + rg * ROW_PAD + ml * DSUB;
    float* myv1 = sv + (rg + 16) * ROW_PAD + ml * DSUB;

    float va[16], vb[16];
    {
        float4 a0 = *(const float4*)(myv0 + 0);
        float4 a1 = *(const float4*)(myv0 + 4);
        float4 a2 = *(const float4*)(myv0 + 8);
        float4 a3 = *(const float4*)(myv0 + 12);
        va[0]=a0.x; va[1]=a0.y; va[2]=a0.z; va[3]=a0.w;
        va[4]=a1.x; va[5]=a1.y; va[6]=a1.z; va[7]=a1.w;
        va[8]=a2.x; va[9]=a2.y; va[10]=a2.z; va[11]=a2.w;
        va[12]=a3.x; va[13]=a3.y; va[14]=a3.z; va[15]=a3.w;
        float4 b0 = *(const float4*)(myv1 + 0);
        float4 b1 = *(const float4*)(myv1 + 4);
        float4 b2 = *(const float4*)(myv1 + 8);
        float4 b3 = *(const float4*)(myv1 + 12);
        vb[0]=b0.x; vb[1]=b0.y; vb[2]=b0.z; vb[3]=b0.w;
        vb[4]=b1.x; vb[5]=b1.y; vb[6]=b1.z; vb[7]=b1.w;
        vb[8]=b2.x; vb[9]=b2.y; vb[10]=b2.z; vb[11]=b2.w;
        vb[12]=b3.x; vb[13]=b3.y; vb[14]=b3.z; vb[15]=b3.w;
    }

    // v2 per row: frozen sequential chains ascending
    float v2a = 0.0f, v2b = 0.0f;
    #pragma unroll
    for (int d = 0; d < DSUB; d++) v2a = fmaf(va[d], va[d], v2a);
    #pragma unroll
    for (int d = 0; d < DSUB; d++) v2b = fmaf(vb[d], vb[d], v2b);

    // c2 for this m: 4x LDS.128 into regs (pair 16 banks apart -> no conflict)
    float c2v[16];
    {
        const float4* p = (const float4*)(sc2 + ml * KSUB);
        float4 q0 = p[0], q1 = p[1], q2 = p[2], q3 = p[3];
        c2v[0]=q0.x; c2v[1]=q0.y; c2v[2]=q0.z; c2v[3]=q0.w;
        c2v[4]=q1.x; c2v[5]=q1.y; c2v[6]=q1.z; c2v[7]=q1.w;
        c2v[8]=q2.x; c2v[9]=q2.y; c2v[10]=q2.z; c2v[11]=q2.w;
        c2v[12]=q3.x; c2v[13]=q3.y; c2v[14]=q3.z; c2v[15]=q3.w;
    }

    const float* cm = scb + ml * M_PAD;               // uniform per half-warp

    float best_a = 3.402823466e38f, best_b = 3.402823466e38f;
    int   bka = 0, bkb = 0;
    #pragma unroll
    for (int k = 0; k < KSUB; ++k) {
        const float* ck = cm + k * DSUB;
        float4 c0 = *(const float4*)(ck + 0);
        float4 c1 = *(const float4*)(ck + 4);
        float4 c2 = *(const float4*)(ck + 8);
        float4 c3 = *(const float4*)(ck + 12);
        float cw[16] = { c0.x,c0.y,c0.z,c0.w, c1.x,c1.y,c1.z,c1.w,
                         c2.x,c2.y,c2.z,c2.w, c3.x,c3.y,c3.z,c3.w };
        // two independent frozen ascending chains (one LDS set feeds both rows)
        float accA = 0.0f, accB = 0.0f;
        #pragma unroll
        for (int d = 0; d < DSUB; d++) {
            accA = fmaf(va[d], cw[d], accA);
            accB = fmaf(vb[d], cw[d], accB);
        }
        float ta = __fadd_rn(__fsub_rn(v2a, __fmul_rn(2.0f, accA)), c2v[k]);
        if (ta < best_a) { best_a = ta; bka = k; }
        float tb = __fadd_rn(__fsub_rn(v2b, __fmul_rn(2.0f, accB)), c2v[k]);
        if (tb < best_b) { best_b = tb; bkb = k; }
    }

    // ---- winners straight to gmem (4 STG.128 per task; warp stores are
    //      dense at 128B-line granularity since m-pair chunks are adjacent) ----
    const int gm = mh * MHALF + ml;                   // global m
    {
        const float4* gk = (const float4*)(cm + bka * DSUB);
        float4 g0 = gk[0], g1 = gk[1], g2 = gk[2], g3 = gk[3];
        float4* dst = (float4*)(out + (row0 + rg) * D_DIM + gm * DSUB);
        dst[0] = g0; dst[1] = g1; dst[2] = g2; dst[3] = g3;
    }
    {
        const float4* gk = (const float4*)(cm + bkb * DSUB);
        float4 g0 = gk[0], g1 = gk[1], g2 = gk[2], g3 = gk[3];
        float4* dst = (float4*)(out + (row0 + rg + 16) * D_DIM + gm * DSUB);
        dst[0] = g0; dst[1] = g1; dst[2] = g2; dst[3] = g3;
    }
}

extern "C" void kernel_launch(void* const* d_in, const int* in_sizes, int n_in,
                              void* d_out, int out_size)
{
    const float* vecs = (const float*)d_in[0];   // (N, 768) f32
    const float* cb   = (const float*)d_in[1];   // (48, 16, 16) f32
    float*       out  = (float*)d_out;           // (N, 768) f32

    cudaFuncSetAttribute(pq_kernel, cudaFuncAttributeMaxDynamicSharedMemorySize, SMEM_BYTES);
    dim3 grid(N_VECS / NROWS, 2);
    pq_kernel<<<grid, NTHREADS, SMEM_BYTES>>>(vecs, cb, out);
}

// round 11
// speedup vs baseline: 2.3201x; 2.3201x over previous
#include <cuda_runtime.h>

// HakesPQ forward: out[n, m*16:(m+1)*16] = codebooks[m, k*, :]
// k* = argmin_k fl( fl(v2 - fl(2*<v,c_k>)) + |c_k|^2 ), exact fp32 emulation of
// the reference (jax/XLA-CPU): all reductions are sequential fmaf chains over
// d ascending; ties -> lowest k. Arithmetic order is FROZEN (rel_err==0.0).
// N=32768, D=768, M=48, KSUB=16, DSUB=16.
//
// R10: l1tex-bytes round. Warp-uniform m + R=4 rows/thread so each broadcast
// codeword fetch feeds 128 row-tasks (cb crossbar bytes /4 vs R8). Staged
// coalesced in/out (R9's direct STG scatter reverted). 2 CTAs/SM.

#define N_VECS   32768
#define D_DIM    768
#define M_SUB    48
#define KSUB     16
#define DSUB     16

#define MG       8                    // m per CTA (blockIdx.y selects group of 8)
#define COLS     (MG * DSUB)          // 128 v-columns per CTA
#define NROWS    128                  // rows per CTA
#define NTHREADS 256                  // 8 warps; warp w owns m=w, lanes own 4 rows
#define ROW_PAD  132                  // 128+4: bank base 4*row -> conflict-free LDS.128

#define SV_FLOATS   (NROWS * ROW_PAD)          // 16896
#define SCB_FLOATS  (MG * KSUB * DSUB)         // 2048
#define SC2_FLOATS  (MG * KSUB)                // 128
#define SMEM_BYTES  ((SV_FLOATS + SCB_FLOATS + SC2_FLOATS) * 4)   // 76288 B

__global__ void __launch_bounds__(NTHREADS, 2)
pq_kernel(const float* __restrict__ vecs,
          const float* __restrict__ cb,
          float* __restrict__ out)
{
    extern __shared__ float smem[];
    float* sv  = smem;                 // [NROWS][ROW_PAD] v tile (this CTA's 128 cols)
    float* scb = smem + SV_FLOATS;     // [MG][KSUB][DSUB]
    float* sc2 = scb + SCB_FLOATS;     // [MG][KSUB]

    const int tid = threadIdx.x;
    const int mg  = blockIdx.y;                       // 0..5
    const float* cbg = cb + mg * (MG * KSUB * DSUB);

    // ---- codebook group into shared (512 float4, coalesced) ----
    {
        const float4* s = (const float4*)cbg;
        float4*       d = (float4*)scb;
        d[tid]       = s[tid];
        d[tid + 256] = s[tid + 256];
    }
    // ---- |c|^2: one (m,k) per thread, frozen sequential fma chain ----
    if (tid < SC2_FLOATS) {
        const float* c = cbg + tid * DSUB;
        float s = 0.0f;
        #pragma unroll
        for (int d = 0; d < DSUB; d++) s = fmaf(c[d], c[d], s);
        sc2[tid] = s;
    }

    // ---- stage 128 rows x 128 cols in (coalesced float4) ----
    const long long row0 = (long long)blockIdx.x * NROWS;
    const float* vbase = vecs + row0 * D_DIM + mg * COLS;
    #pragma unroll
    for (int j = 0; j < 16; j++) {
        int i  = tid + j * NTHREADS;
        int r  = i >> 5;                              // 0..127
        int c4 = i & 31;
        *(float4*)(sv + r * ROW_PAD + c4 * 4) =
            *(const float4*)(vbase + (long long)r * D_DIM + c4 * 4);
    }
    __syncthreads();

    const int w = tid >> 5;            // warp-uniform m (local)
    const int l = tid & 31;            // rows l, l+32, l+64, l+96

    // ---- load 4 rows' v chunks + frozen v2 chains ----
    float v[4][16];
    float v2[4];
    #pragma unroll
    for (int g = 0; g < 4; g++) {
        const float* p = sv + (l + 32 * g) * ROW_PAD + w * DSUB;
        float4 a0 = *(const float4*)(p + 0);
        float4 a1 = *(const float4*)(p + 4);
        float4 a2 = *(const float4*)(p + 8);
        float4 a3 = *(const float4*)(p + 12);
        v[g][0]=a0.x;  v[g][1]=a0.y;  v[g][2]=a0.z;  v[g][3]=a0.w;
        v[g][4]=a1.x;  v[g][5]=a1.y;  v[g][6]=a1.z;  v[g][7]=a1.w;
        v[g][8]=a2.x;  v[g][9]=a2.y;  v[g][10]=a2.z; v[g][11]=a2.w;
        v[g][12]=a3.x; v[g][13]=a3.y; v[g][14]=a3.z; v[g][15]=a3.w;
        float s = 0.0f;
        #pragma unroll
        for (int d = 0; d < DSUB; d++) s = fmaf(v[g][d], v[g][d], s);
        v2[g] = s;
    }

    const float* cm  = scb + w * (KSUB * DSUB);   // warp-uniform -> broadcast
    const float* c2m = sc2 + w * KSUB;

    float best[4] = { 3.402823466e38f, 3.402823466e38f,
                      3.402823466e38f, 3.402823466e38f };
    int   bk[4]   = { 0, 0, 0, 0 };

    #pragma unroll
    for (int k = 0; k < KSUB; ++k) {
        const float* ck = cm + k * DSUB;
        float4 c0 = *(const float4*)(ck + 0);     // broadcast LDS.128 x4,
        float4 c1 = *(const float4*)(ck + 4);     // amortized over 4 rows
        float4 c2 = *(const float4*)(ck + 8);
        float4 c3 = *(const float4*)(ck + 12);
        float cw[16] = { c0.x,c0.y,c0.z,c0.w, c1.x,c1.y,c1.z,c1.w,
                         c2.x,c2.y,c2.z,c2.w, c3.x,c3.y,c3.z,c3.w };
        float acc0 = 0.0f, acc1 = 0.0f, acc2a = 0.0f, acc3 = 0.0f;
        #pragma unroll
        for (int d = 0; d < DSUB; d++) {          // 4 independent frozen chains
            acc0  = fmaf(v[0][d], cw[d], acc0);
            acc1  = fmaf(v[1][d], cw[d], acc1);
            acc2a = fmaf(v[2][d], cw[d], acc2a);
            acc3  = fmaf(v[3][d], cw[d], acc3);
        }
        float c2k = c2m[k];                       // broadcast scalar
        // frozen elementwise ops, RN each step; strict < ascending k
        float t0 = __fadd_rn(__fsub_rn(v2[0], __fmul_rn(2.0f, acc0 )), c2k);
        if (t0 < best[0]) { best[0] = t0; bk[0] = k; }
        float t1 = __fadd_rn(__fsub_rn(v2[1], __fmul_rn(2.0f, acc1 )), c2k);
        if (t1 < best[1]) { best[1] = t1; bk[1] = k; }
        float t2 = __fadd_rn(__fsub_rn(v2[2], __fmul_rn(2.0f, acc2a)), c2k);
        if (t2 < best[2]) { best[2] = t2; bk[2] = k; }
        float t3 = __fadd_rn(__fsub_rn(v2[3], __fmul_rn(2.0f, acc3 )), c2k);
        if (t3 < best[3]) { best[3] = t3; bk[3] = k; }
    }

    // ---- gather winners into own (dead) v regions in shared ----
    #pragma unroll
    for (int g = 0; g < 4; g++) {
        const float4* gk = (const float4*)(cm + bk[g] * DSUB);
        float4 g0 = gk[0], g1 = gk[1], g2 = gk[2], g3 = gk[3];
        float* p = sv + (l + 32 * g) * ROW_PAD + w * DSUB;
        *(float4*)(p + 0)  = g0;
        *(float4*)(p + 4)  = g1;
        *(float4*)(p + 8)  = g2;
        *(float4*)(p + 12) = g3;
    }
    __syncthreads();

    // ---- stage out (coalesced float4) ----
    float* obase = out + row0 * D_DIM + mg * COLS;
    #pragma unroll
    for (int j = 0; j < 16; j++) {
        int i  = tid + j * NTHREADS;
        int r  = i >> 5;
        int c4 = i & 31;
        *(float4*)(obase + (long long)r * D_DIM + c4 * 4) =
            *(const float4*)(sv + r * ROW_PAD + c4 * 4);
    }
}

extern "C" void kernel_launch(void* const* d_in, const int* in_sizes, int n_in,
                              void* d_out, int out_size)
{
    const float* vecs = (const float*)d_in[0];   // (N, 768) f32
    const float* cb   = (const float*)d_in[1];   // (48, 16, 16) f32
    float*       out  = (float*)d_out;           // (N, 768) f32

    cudaFuncSetAttribute(pq_kernel, cudaFuncAttributeMaxDynamicSharedMemorySize, SMEM_BYTES);
    dim3 grid(N_VECS / NROWS, M_SUB / MG);       // (256, 6)
    pq_kernel<<<grid, NTHREADS, SMEM_BYTES>>>(vecs, cb, out);
}

// round 13
// speedup vs baseline: 2.3700x; 1.0215x over previous
#include <cuda_runtime.h>
#include <stdint.h>

// HakesPQ forward: out[n, m*16:(m+1)*16] = codebooks[m, k*, :]
// k* = argmin_k fl( fl(v2 - fl(2*<v,c_k>)) + |c_k|^2 ), exact fp32 emulation of
// the reference (jax/XLA-CPU): all reductions are sequential fmaf chains over
// d ascending; ties -> lowest k. Arithmetic order is FROZEN (rel_err==0.0).
// fma.rn.f32x2 = two independent IEEE fp32 RN FMAs; packing ROW-pairs into the
// two lanes keeps each row's chain bitwise identical to the scalar chain.
// N=32768, D=768, M=48, KSUB=16, DSUB=16.
//
// R11: (a) index-based output: store bk bytes, gather winners from scb directly
// in the coalesced out-loop (removes gather-to-sv + winner STS + stage-out LDS);
// (b) row-pair FFMA2 halves dot-product fma instrs; (c) cb k-stride 20 spreads
// out-phase gather banks. Warp-uniform m, R=4 rows/thread, 2 CTAs/SM.

#define N_VECS   32768
#define D_DIM    768
#define M_SUB    48
#define KSUB     16
#define DSUB     16

#define MG       8                    // m per CTA (blockIdx.y selects group)
#define COLS     (MG * DSUB)          // 128 v-columns per CTA
#define NROWS    128                  // rows per CTA
#define NTHREADS 256                  // 8 warps; warp w owns m=w, lanes own 4 rows
#define ROW_PAD  132                  // conflict-free LDS.128 on v tile
#define K_STRIDE 20                   // codeword stride in floats (bank spread)
#define M_STRIDE (KSUB * K_STRIDE)    // 320 floats per m
#define IDX_PAD  132                  // sidx row pad in bytes (bank spread)

#define SV_FLOATS   (NROWS * ROW_PAD)          // 16896
#define SCB_FLOATS  (MG * M_STRIDE)            // 2560
#define SC2_FLOATS  (MG * KSUB)                // 128
#define SIDX_BYTES  (MG * IDX_PAD)             // 1056
// floats area + index bytes
#define SMEM_BYTES  ((SV_FLOATS + SCB_FLOATS + SC2_FLOATS) * 4 + SIDX_BYTES)

// ---- packed f32x2 helpers ----
__device__ __forceinline__ unsigned long long ffma2(unsigned long long a,
                                                    unsigned long long b,
                                                    unsigned long long c) {
    unsigned long long d;
    asm("fma.rn.f32x2 %0, %1, %2, %3;" : "=l"(d) : "l"(a), "l"(b), "l"(c));
    return d;
}
__device__ __forceinline__ unsigned long long packf2(float lo, float hi) {
    unsigned long long r;
    asm("mov.b64 %0, {%1, %2};" : "=l"(r) : "f"(lo), "f"(hi));
    return r;
}
__device__ __forceinline__ void unpack2(unsigned long long a, float& lo, float& hi) {
    asm("mov.b64 {%0, %1}, %2;" : "=f"(lo), "=f"(hi) : "l"(a));
}

__global__ void __launch_bounds__(NTHREADS, 2)
pq_kernel(const float* __restrict__ vecs,
          const float* __restrict__ cb,
          float* __restrict__ out)
{
    extern __shared__ float smem[];
    float*   sv   = smem;                          // [NROWS][ROW_PAD]
    float*   scb  = smem + SV_FLOATS;              // [MG][KSUB][K_STRIDE]
    float*   sc2  = scb + SCB_FLOATS;              // [MG][KSUB]
    uint8_t* sidx = (uint8_t*)(sc2 + SC2_FLOATS);  // [MG][IDX_PAD]

    const int tid = threadIdx.x;
    const int mg  = blockIdx.y;                    // 0..5
    const float* cbg = cb + mg * (MG * KSUB * DSUB);

    // ---- codebook group into shared, k-stride 20 (coalesced float4 src) ----
    {
        const float4* s = (const float4*)cbg;      // 512 float4
        #pragma unroll
        for (int t = 0; t < 2; t++) {
            int i = tid + t * NTHREADS;
            int q = i & 3;                         // quarter within codeword
            int k = (i >> 2) & 15;
            int m = i >> 6;
            *(float4*)(scb + m * M_STRIDE + k * K_STRIDE + q * 4) = s[i];
        }
    }
    // ---- |c|^2: one (m,k) per thread, frozen sequential fma chain ----
    if (tid < SC2_FLOATS) {
        const float* c = cbg + tid * DSUB;
        float s = 0.0f;
        #pragma unroll
        for (int d = 0; d < DSUB; d++) s = fmaf(c[d], c[d], s);
        sc2[tid] = s;
    }

    // ---- stage 128 rows x 128 cols in (coalesced float4) ----
    const long long row0 = (long long)blockIdx.x * NROWS;
    const float* vbase = vecs + row0 * D_DIM + mg * COLS;
    #pragma unroll
    for (int j = 0; j < 16; j++) {
        int i  = tid + j * NTHREADS;
        int r  = i >> 5;
        int c4 = i & 31;
        *(float4*)(sv + r * ROW_PAD + c4 * 4) =
            *(const float4*)(vbase + (long long)r * D_DIM + c4 * 4);
    }
    __syncthreads();

    const int w = tid >> 5;            // warp-uniform local m
    const int l = tid & 31;            // rows l, l+32, l+64, l+96

    // ---- load 4 rows, frozen v2 chains, pack row-pairs ----
    float v[4][16];
    float v2[4];
    #pragma unroll
    for (int g = 0; g < 4; g++) {
        const float* p = sv + (l + 32 * g) * ROW_PAD + w * DSUB;
        float4 a0 = *(const float4*)(p + 0);
        float4 a1 = *(const float4*)(p + 4);
        float4 a2 = *(const float4*)(p + 8);
        float4 a3 = *(const float4*)(p + 12);
        v[g][0]=a0.x;  v[g][1]=a0.y;  v[g][2]=a0.z;  v[g][3]=a0.w;
        v[g][4]=a1.x;  v[g][5]=a1.y;  v[g][6]=a1.z;  v[g][7]=a1.w;
        v[g][8]=a2.x;  v[g][9]=a2.y;  v[g][10]=a2.z; v[g][11]=a2.w;
        v[g][12]=a3.x; v[g][13]=a3.y; v[g][14]=a3.z; v[g][15]=a3.w;
        float s = 0.0f;
        #pragma unroll
        for (int d = 0; d < DSUB; d++) s = fmaf(v[g][d], v[g][d], s);
        v2[g] = s;
    }
    unsigned long long vp0[16], vp1[16];           // lanes = (row g0, row g1)
    #pragma unroll
    for (int d = 0; d < DSUB; d++) {
        vp0[d] = packf2(v[0][d], v[1][d]);
        vp1[d] = packf2(v[2][d], v[3][d]);
    }

    const float* cm  = scb + w * M_STRIDE;         // warp-uniform -> broadcast
    const float* c2m = sc2 + w * KSUB;

    float best[4] = { 3.402823466e38f, 3.402823466e38f,
                      3.402823466e38f, 3.402823466e38f };
    int   bk[4]   = { 0, 0, 0, 0 };

    #pragma unroll
    for (int k = 0; k < KSUB; ++k) {
        const float* ck = cm + k * K_STRIDE;
        float4 c0 = *(const float4*)(ck + 0);      // broadcast LDS.128 x4
        float4 c1 = *(const float4*)(ck + 4);
        float4 c2 = *(const float4*)(ck + 8);
        float4 c3 = *(const float4*)(ck + 12);
        float cw[16] = { c0.x,c0.y,c0.z,c0.w, c1.x,c1.y,c1.z,c1.w,
                         c2.x,c2.y,c2.z,c2.w, c3.x,c3.y,c3.z,c3.w };
        unsigned long long a0 = 0ULL, a1 = 0ULL;
        #pragma unroll
        for (int d = 0; d < DSUB; d++) {           // frozen ascending chains,
            unsigned long long cp = packf2(cw[d], cw[d]);   // lanes independent
            a0 = ffma2(vp0[d], cp, a0);
            a1 = ffma2(vp1[d], cp, a1);
        }
        float s0, s1, s2, s3;
        unpack2(a0, s0, s1);
        unpack2(a1, s2, s3);
        float c2k = c2m[k];
        // frozen elementwise ops, RN each step; strict < -> first max wins
        float t0 = __fadd_rn(__fsub_rn(v2[0], __fmul_rn(2.0f, s0)), c2k);
        if (t0 < best[0]) { best[0] = t0; bk[0] = k; }
        float t1 = __fadd_rn(__fsub_rn(v2[1], __fmul_rn(2.0f, s1)), c2k);
        if (t1 < best[1]) { best[1] = t1; bk[1] = k; }
        float t2 = __fadd_rn(__fsub_rn(v2[2], __fmul_rn(2.0f, s2)), c2k);
        if (t2 < best[2]) { best[2] = t2; bk[2] = k; }
        float t3 = __fadd_rn(__fsub_rn(v2[3], __fmul_rn(2.0f, s3)), c2k);
        if (t3 < best[3]) { best[3] = t3; bk[3] = k; }
    }

    // ---- publish winner indices (tiny: 4 bytes/thread, conflict-free) ----
    #pragma unroll
    for (int g = 0; g < 4; g++)
        sidx[w * IDX_PAD + (l + 32 * g)] = (uint8_t)bk[g];
    __syncthreads();

    // ---- coalesced output: gather winning codeword from scb, STG direct ----
    float* obase = out + row0 * D_DIM + mg * COLS;
    #pragma unroll
    for (int j = 0; j < 16; j++) {
        int i  = tid + j * NTHREADS;
        int r  = i >> 5;                           // warp covers one row
        int c4 = i & 31;
        int m  = c4 >> 2;                          // 4 lanes per m
        int q  = c4 & 3;
        int k  = sidx[m * IDX_PAD + r];            // 8 distinct bytes/warp, 1 wf
        float4 gv = *(const float4*)(scb + m * M_STRIDE + k * K_STRIDE + q * 4);
        *(float4*)(obase + (long long)r * D_DIM + c4 * 4) = gv;   // 512B/warp contiguous
    }
}

extern "C" void kernel_launch(void* const* d_in, const int* in_sizes, int n_in,
                              void* d_out, int out_size)
{
    const float* vecs = (const float*)d_in[0];   // (N, 768) f32
    const float* cb   = (const float*)d_in[1];   // (48, 16, 16) f32
    float*       out  = (float*)d_out;           // (N, 768) f32

    cudaFuncSetAttribute(pq_kernel, cudaFuncAttributeMaxDynamicSharedMemorySize, SMEM_BYTES);
    dim3 grid(N_VECS / NROWS, M_SUB / MG);       // (256, 6)
    pq_kernel<<<grid, NTHREADS, SMEM_BYTES>>>(vecs, cb, out);
}

// round 15
// speedup vs baseline: 2.4633x; 1.0394x over previous
#include <cuda_runtime.h>
#include <stdint.h>

// HakesPQ forward: out[n, m*16:(m+1)*16] = codebooks[m, k*, :]
// k* = argmin_k fl( fl(v2 - fl(2*<v,c_k>)) + |c_k|^2 ), exact fp32 emulation of
// the reference (jax/XLA-CPU): all reductions are sequential fmaf chains over
// d ascending; ties -> lowest k. Arithmetic order is FROZEN (rel_err==0.0).
// N=32768, D=768, M=48, KSUB=16, DSUB=16.
//
// R13 = R10's scalar 4-chain inner loop (alu 13%) + R12's index-based output
// path (L1 50.7%): no packed-operand ALU movs, no u64 register pressure.
// Warp-uniform m, R=4 rows/thread, staged coalesced in, idx-gather out, 2 CTAs/SM.

#define N_VECS   32768
#define D_DIM    768
#define M_SUB    48
#define KSUB     16
#define DSUB     16

#define MG       8                    // m per CTA (blockIdx.y selects group)
#define COLS     (MG * DSUB)          // 128 v-columns per CTA
#define NROWS    128                  // rows per CTA
#define NTHREADS 256                  // 8 warps; warp w owns m=w, lanes own 4 rows
#define ROW_PAD  132                  // conflict-free LDS.128 on v tile
#define K_STRIDE 20                   // codeword stride in floats (bank spread)
#define M_STRIDE (KSUB * K_STRIDE)    // 320 floats per m
#define IDX_PAD  132                  // sidx row pad in bytes (bank spread)

#define SV_FLOATS   (NROWS * ROW_PAD)          // 16896
#define SCB_FLOATS  (MG * M_STRIDE)            // 2560
#define SC2_FLOATS  (MG * KSUB)                // 128
#define SIDX_BYTES  (MG * IDX_PAD)             // 1056
#define SMEM_BYTES  ((SV_FLOATS + SCB_FLOATS + SC2_FLOATS) * 4 + SIDX_BYTES)

__global__ void __launch_bounds__(NTHREADS, 2)
pq_kernel(const float* __restrict__ vecs,
          const float* __restrict__ cb,
          float* __restrict__ out)
{
    extern __shared__ float smem[];
    float*   sv   = smem;                          // [NROWS][ROW_PAD]
    float*   scb  = smem + SV_FLOATS;              // [MG][KSUB][K_STRIDE]
    float*   sc2  = scb + SCB_FLOATS;              // [MG][KSUB]
    uint8_t* sidx = (uint8_t*)(sc2 + SC2_FLOATS);  // [MG][IDX_PAD]

    const int tid = threadIdx.x;
    const int mg  = blockIdx.y;                    // 0..5
    const float* cbg = cb + mg * (MG * KSUB * DSUB);

    // ---- codebook group into shared, k-stride 20 (coalesced float4 src) ----
    {
        const float4* s = (const float4*)cbg;      // 512 float4
        #pragma unroll
        for (int t = 0; t < 2; t++) {
            int i = tid + t * NTHREADS;
            int q = i & 3;                         // quarter within codeword
            int k = (i >> 2) & 15;
            int m = i >> 6;
            *(float4*)(scb + m * M_STRIDE + k * K_STRIDE + q * 4) = s[i];
        }
    }
    // ---- |c|^2: one (m,k) per thread, frozen sequential fma chain ----
    if (tid < SC2_FLOATS) {
        const float* c = cbg + tid * DSUB;
        float s = 0.0f;
        #pragma unroll
        for (int d = 0; d < DSUB; d++) s = fmaf(c[d], c[d], s);
        sc2[tid] = s;
    }

    // ---- stage 128 rows x 128 cols in (coalesced float4) ----
    const long long row0 = (long long)blockIdx.x * NROWS;
    const float* vbase = vecs + row0 * D_DIM + mg * COLS;
    #pragma unroll
    for (int j = 0; j < 16; j++) {
        int i  = tid + j * NTHREADS;
        int r  = i >> 5;
        int c4 = i & 31;
        *(float4*)(sv + r * ROW_PAD + c4 * 4) =
            *(const float4*)(vbase + (long long)r * D_DIM + c4 * 4);
    }
    __syncthreads();

    const int w = tid >> 5;            // warp-uniform local m
    const int l = tid & 31;            // rows l, l+32, l+64, l+96

    // ---- load 4 rows' v chunks + frozen v2 chains ----
    float v[4][16];
    float v2[4];
    #pragma unroll
    for (int g = 0; g < 4; g++) {
        const float* p = sv + (l + 32 * g) * ROW_PAD + w * DSUB;
        float4 a0 = *(const float4*)(p + 0);
        float4 a1 = *(const float4*)(p + 4);
        float4 a2 = *(const float4*)(p + 8);
        float4 a3 = *(const float4*)(p + 12);
        v[g][0]=a0.x;  v[g][1]=a0.y;  v[g][2]=a0.z;  v[g][3]=a0.w;
        v[g][4]=a1.x;  v[g][5]=a1.y;  v[g][6]=a1.z;  v[g][7]=a1.w;
        v[g][8]=a2.x;  v[g][9]=a2.y;  v[g][10]=a2.z; v[g][11]=a2.w;
        v[g][12]=a3.x; v[g][13]=a3.y; v[g][14]=a3.z; v[g][15]=a3.w;
        float s = 0.0f;
        #pragma unroll
        for (int d = 0; d < DSUB; d++) s = fmaf(v[g][d], v[g][d], s);
        v2[g] = s;
    }

    const float* cm  = scb + w * M_STRIDE;         // warp-uniform -> broadcast
    const float* c2m = sc2 + w * KSUB;

    float best[4] = { 3.402823466e38f, 3.402823466e38f,
                      3.402823466e38f, 3.402823466e38f };
    int   bk[4]   = { 0, 0, 0, 0 };

    #pragma unroll
    for (int k = 0; k < KSUB; ++k) {
        const float* ck = cm + k * K_STRIDE;
        float4 c0 = *(const float4*)(ck + 0);      // broadcast LDS.128 x4,
        float4 c1 = *(const float4*)(ck + 4);      // amortized over 4 rows
        float4 c2 = *(const float4*)(ck + 8);
        float4 c3 = *(const float4*)(ck + 12);
        float cw[16] = { c0.x,c0.y,c0.z,c0.w, c1.x,c1.y,c1.z,c1.w,
                         c2.x,c2.y,c2.z,c2.w, c3.x,c3.y,c3.z,c3.w };
        float acc0 = 0.0f, acc1 = 0.0f, acc2a = 0.0f, acc3 = 0.0f;
        #pragma unroll
        for (int d = 0; d < DSUB; d++) {           // 4 independent frozen chains
            acc0  = fmaf(v[0][d], cw[d], acc0);
            acc1  = fmaf(v[1][d], cw[d], acc1);
            acc2a = fmaf(v[2][d], cw[d], acc2a);
            acc3  = fmaf(v[3][d], cw[d], acc3);
        }
        float c2k = c2m[k];                        // broadcast scalar
        // frozen elementwise ops, RN each step; strict < -> first max wins
        float t0 = __fadd_rn(__fsub_rn(v2[0], __fmul_rn(2.0f, acc0 )), c2k);
        if (t0 < best[0]) { best[0] = t0; bk[0] = k; }
        float t1 = __fadd_rn(__fsub_rn(v2[1], __fmul_rn(2.0f, acc1 )), c2k);
        if (t1 < best[1]) { best[1] = t1; bk[1] = k; }
        float t2 = __fadd_rn(__fsub_rn(v2[2], __fmul_rn(2.0f, acc2a)), c2k);
        if (t2 < best[2]) { best[2] = t2; bk[2] = k; }
        float t3 = __fadd_rn(__fsub_rn(v2[3], __fmul_rn(2.0f, acc3 )), c2k);
        if (t3 < best[3]) { best[3] = t3; bk[3] = k; }
    }

    // ---- publish winner indices (4 bytes/thread, conflict-free) ----
    #pragma unroll
    for (int g = 0; g < 4; g++)
        sidx[w * IDX_PAD + (l + 32 * g)] = (uint8_t)bk[g];
    __syncthreads();

    // ---- coalesced output: gather winning codeword from scb, STG direct ----
    float* obase = out + row0 * D_DIM + mg * COLS;
    #pragma unroll
    for (int j = 0; j < 16; j++) {
        int i  = tid + j * NTHREADS;
        int r  = i >> 5;                           // warp covers one row
        int c4 = i & 31;
        int m  = c4 >> 2;                          // 4 lanes per m
        int q  = c4 & 3;
        int k  = sidx[m * IDX_PAD + r];            // 8 distinct bytes/warp
        float4 gv = *(const float4*)(scb + m * M_STRIDE + k * K_STRIDE + q * 4);
        *(float4*)(obase + (long long)r * D_DIM + c4 * 4) = gv;   // 512B/warp contiguous
    }
}

extern "C" void kernel_launch(void* const* d_in, const int* in_sizes, int n_in,
                              void* d_out, int out_size)
{
    const float* vecs = (const float*)d_in[0];   // (N, 768) f32
    const float* cb   = (const float*)d_in[1];   // (48, 16, 16) f32
    float*       out  = (float*)d_out;           // (N, 768) f32

    cudaFuncSetAttribute(pq_kernel, cudaFuncAttributeMaxDynamicSharedMemorySize, SMEM_BYTES);
    dim3 grid(N_VECS / NROWS, M_SUB / MG);       // (256, 6)
    pq_kernel<<<grid, NTHREADS, SMEM_BYTES>>>(vecs, cb, out);
}